// round 12
// baseline (speedup 1.0000x reference)
#include <cuda_runtime.h>
#include <cstdint>
#include <math.h>

#define TT 2048
#define CC 2048
#define HH 16
#define DN 128
#define DR 64
#define DV 128
#define QKD 192
#define RQ 1536
#define RKV 512
#define EPSF 1e-6f
#define SCALEF 0.07216878364870323f  // 192^-0.5

// ---------------- scratch (device globals; no allocation allowed) ----------------
__device__ float g_qlat[TT * RQ];
__device__ float g_q[TT * HH * QKD];
__device__ float g_kvpe[TT * (RKV + DR)];
__device__ float g_kvlat[TT * RKV];
__device__ float g_kvb[TT * HH * (DN + DV)];
__device__ float g_y[TT * CC];

// ---------------- helpers ----------------
__device__ __forceinline__ float tf32r(float f) {
    unsigned u;
    asm("cvt.rna.tf32.f32 %0, %1;" : "=r"(u) : "f"(f));
    return __uint_as_float(u);
}
__device__ __forceinline__ unsigned fbits(float f) { return __float_as_uint(f); }

__device__ __forceinline__ void mma_tf32(float c[4], const unsigned a[4], const unsigned b[2]) {
    asm volatile(
        "mma.sync.aligned.m16n8k8.row.col.f32.tf32.tf32.f32 "
        "{%0,%1,%2,%3}, {%4,%5,%6,%7}, {%8,%9}, {%0,%1,%2,%3};"
        : "+f"(c[0]), "+f"(c[1]), "+f"(c[2]), "+f"(c[3])
        : "r"(a[0]), "r"(a[1]), "r"(a[2]), "r"(a[3]), "r"(b[0]), "r"(b[1]));
}

__device__ __forceinline__ void cpa16(float* s, const float* g) {
    unsigned sa = (unsigned)__cvta_generic_to_shared(s);
    asm volatile("cp.async.cg.shared.global [%0], [%1], 16;" :: "r"(sa), "l"(g) : "memory");
}
__device__ __forceinline__ void cp_commit() { asm volatile("cp.async.commit_group;" ::: "memory"); }
template <int N>
__device__ __forceinline__ void cp_wait() { asm volatile("cp.async.wait_group %0;" :: "n"(N) : "memory"); }

// round a linear smem region [buf, buf+n) in-place, n % 4 == 0, strided by all threads
__device__ __forceinline__ void round_smem(float* buf, int n, int tid, int nthr) {
    for (int i = tid * 4; i < n; i += nthr * 4) {
        float4 v = *(float4*)(buf + i);
        *(float4*)(buf + i) = make_float4(tf32r(v.x), tf32r(v.y), tf32r(v.z), tf32r(v.w));
    }
}

// ---------------- tensor-core GEMM: C[M,N] = A[M,K] @ B[N,K]^T + bias ----------------
// Block 128 x (16*NF), 128 threads (4 warps, 2x2 grid), warp tile 64 x (8*NF).
// 3-stage cp.async pipeline; whole stage rna-rounded once after landing.
#define GPIT 36

template <int NF>
__global__ void __launch_bounds__(128, 2) gemm_tc(
    const float* __restrict__ A, const float* __restrict__ B,
    const float* __restrict__ bias, float* __restrict__ Cm,
    int K)
{
    constexpr int BM = 128, BN = 16 * NF;
    constexpr int ASTAGE = BM * GPIT, BSTAGE = BN * GPIT;

    extern __shared__ float sh[];
    float* As = sh;
    float* Bs = sh + 3 * ASTAGE;

    int tid = threadIdx.x;
    int lane = tid & 31, warp = tid >> 5;
    int wm = warp >> 1, wn = warp & 1;
    int m0 = blockIdx.y * BM, n0 = blockIdx.x * BN;
    int N = gridDim.x * BN;

    auto load_stage = [&](int s, int k0) {
#pragma unroll
        for (int i = 0; i < (BM * 8) / 128; i++) {
            int idx = i * 128 + tid, r = idx >> 3, c = (idx & 7) << 2;
            cpa16(As + s * ASTAGE + r * GPIT + c, A + (size_t)(m0 + r) * K + k0 + c);
        }
#pragma unroll
        for (int i = 0; i < (BN * 8) / 128; i++) {
            int idx = i * 128 + tid, r = idx >> 3, c = (idx & 7) << 2;
            cpa16(Bs + s * BSTAGE + r * GPIT + c, B + (size_t)(n0 + r) * K + k0 + c);
        }
    };

    float acc[4][NF][4];
#pragma unroll
    for (int i = 0; i < 4; i++)
#pragma unroll
        for (int j = 0; j < NF; j++)
#pragma unroll
            for (int k = 0; k < 4; k++) acc[i][j][k] = 0.f;

    load_stage(0, 0); cp_commit();
    load_stage(1, 32); cp_commit();

    int nIter = K >> 5;
    for (int it = 0; it < nIter; it++) {
        cp_wait<1>();
        __syncthreads();
        if (it + 2 < nIter) load_stage((it + 2) % 3, (it + 2) << 5);
        cp_commit();

        float* Ab = As + (it % 3) * ASTAGE;
        float* Bb = Bs + (it % 3) * BSTAGE;
        // one-pass rna rounding of the freshly-landed stage (incl. harmless padding)
        round_smem(Ab, ASTAGE, tid, 128);
        round_smem(Bb, BSTAGE, tid, 128);
        __syncthreads();

#pragma unroll
        for (int ks = 0; ks < 4; ks++) {
            int kidx = ks * 8 + (lane & 3);
            unsigned af[4][4], bf[NF][2];
            int arow = wm * 64 + (lane >> 2);
#pragma unroll
            for (int mf = 0; mf < 4; mf++) {
                const float* p = Ab + (arow + mf * 16) * GPIT + kidx;
                af[mf][0] = fbits(p[0]);
                af[mf][1] = fbits(p[8 * GPIT]);
                af[mf][2] = fbits(p[4]);
                af[mf][3] = fbits(p[8 * GPIT + 4]);
            }
            int brow = wn * (NF * 8) + (lane >> 2);
#pragma unroll
            for (int nf = 0; nf < NF; nf++) {
                const float* p = Bb + (brow + nf * 8) * GPIT + kidx;
                bf[nf][0] = fbits(p[0]);
                bf[nf][1] = fbits(p[4]);
            }
#pragma unroll
            for (int mf = 0; mf < 4; mf++)
#pragma unroll
                for (int nf = 0; nf < NF; nf++)
                    mma_tf32(acc[mf][nf], af[mf], bf[nf]);
        }
    }

#pragma unroll
    for (int mf = 0; mf < 4; mf++) {
        int row0 = m0 + wm * 64 + mf * 16 + (lane >> 2);
#pragma unroll
        for (int nf = 0; nf < NF; nf++) {
            int col = n0 + wn * (NF * 8) + nf * 8 + 2 * (lane & 3);
            float b0 = bias[col], b1 = bias[col + 1];
            *(float2*)&Cm[(size_t)row0 * N + col] =
                make_float2(acc[mf][nf][0] + b0, acc[mf][nf][1] + b1);
            *(float2*)&Cm[(size_t)(row0 + 8) * N + col] =
                make_float2(acc[mf][nf][2] + b0, acc[mf][nf][3] + b1);
        }
    }
}

static inline int gsmem(int NF) { return 3 * (128 + 16 * NF) * GPIT * 4; }

// ---------------- RMSNorm (row-wise) ----------------
__global__ void __launch_bounds__(256) rmsnorm_kernel(
    const float* __restrict__ src, int srcStride,
    float* __restrict__ dst, int dstStride,
    const float* __restrict__ w, int cols)
{
    int row = blockIdx.x;
    const float* s = src + (size_t)row * srcStride;
    float* d = dst + (size_t)row * dstStride;
    float sum = 0.f;
    for (int i = threadIdx.x; i < cols; i += 256) { float v = s[i]; sum += v * v; }
    __shared__ float red[256];
    red[threadIdx.x] = sum;
    __syncthreads();
    for (int o = 128; o > 0; o >>= 1) {
        if (threadIdx.x < o) red[threadIdx.x] += red[threadIdx.x + o];
        __syncthreads();
    }
    float inv = rsqrtf(red[0] / (float)cols + EPSF);
    for (int i = threadIdx.x; i < cols; i += 256) d[i] = s[i] * inv * w[i];
}

// ---------------- RoPE ----------------
__global__ void rope_q_kernel(const float* __restrict__ freqs) {
    int idx = blockIdx.x * blockDim.x + threadIdx.x;
    if (idx >= TT * HH * 32) return;
    int i = idx & 31;
    int h = (idx >> 5) & 15;
    int t = idx >> 9;
    float f = freqs[t * 32 + i];
    float c = cosf(f), s = sinf(f);
    float* p = g_q + (size_t)t * (HH * QKD) + h * QKD + DN + 2 * i;
    float x0 = p[0], x1 = p[1];
    p[0] = x0 * c - x1 * s;
    p[1] = x0 * s + x1 * c;
}

__global__ void rope_k_kernel(const float* __restrict__ freqs) {
    int idx = blockIdx.x * blockDim.x + threadIdx.x;
    if (idx >= TT * 32) return;
    int i = idx & 31;
    int t = idx >> 5;
    float f = freqs[t * 32 + i];
    float c = cosf(f), s = sinf(f);
    float* p = g_kvpe + (size_t)t * (RKV + DR) + RKV + 2 * i;
    float x0 = p[0], x1 = p[1];
    p[0] = x0 * c - x1 * s;
    p[1] = x0 * s + x1 * c;
}

// ---------------- Flash attention (mma.sync tf32, cp.async double-buffered) ----------------
// All smem tiles rna-rounded in one linear pass after landing; hot loops cvt-free.
#define AQ (64 * 192)
#define AV (64 * 128)
#define APP 68
#define ATTN_FLOATS (3 * AQ + 2 * AV + 64 * APP + 192)
#define ATTN_SMEM (ATTN_FLOATS * 4)

__global__ void __launch_bounds__(256, 1) attn_tc(
    const float* __restrict__ q, const float* __restrict__ kvb,
    const float* __restrict__ kvpe, float* __restrict__ y)
{
    extern __shared__ float sm[];
    float* Qs = sm;
    float* Ks = sm + AQ;
    float* Vs = sm + 3 * AQ;
    float* Ps = sm + 3 * AQ + 2 * AV;
    float* m_s = Ps + 64 * APP;
    float* l_s = m_s + 64;
    float* al_s = l_s + 64;

    int h = blockIdx.y;
    int qt = gridDim.x - 1 - blockIdx.x;
    int tid = threadIdx.x, lane = tid & 31, warp = tid >> 5;
    int wm = warp >> 1, wn = warp & 1;

    int lr = tid >> 2;
    int lq = tid & 3;

    auto load_kv = [&](int buf, int kt2) {
        int t = kt2 * 64 + lr;
        const float* gk = kvb + (size_t)t * 4096 + h * 256;
        const float* gp = kvpe + (size_t)t * 576 + 512;
        float* Kb = Ks + buf * AQ + lr * 192;
        int sw = 4 * (lr & 7);
#pragma unroll
        for (int j = 0; j < 12; j++) {
            int c4 = lq * 12 + j;
            const float* src = (c4 < 32) ? (gk + 4 * c4) : (gp + 4 * (c4 - 32));
            cpa16(&Kb[(4 * c4) ^ sw], src);
        }
        float* Vb = Vs + buf * AV + lr * 128;
        int swv = 8 * (lr & 3);
#pragma unroll
        for (int j = 0; j < 8; j++) {
            int c4 = lq * 8 + j;
            cpa16(&Vb[(4 * c4) ^ swv], gk + 128 + 4 * c4);
        }
    };

    {
        const float* gq = q + (size_t)(qt * 64 + lr) * (HH * QKD) + h * QKD;
        float* Qr = Qs + lr * 192;
        int sw = 4 * (lr & 7);
#pragma unroll
        for (int j = 0; j < 12; j++) {
            int c4 = lq * 12 + j;
            cpa16(&Qr[(4 * c4) ^ sw], gq + 4 * c4);
        }
    }
    load_kv(0, 0);
    cp_commit();

    if (tid < 64) { m_s[tid] = -1e30f; l_s[tid] = 0.f; }

    float oacc[8][4];
#pragma unroll
    for (int i = 0; i < 8; i++)
#pragma unroll
        for (int j = 0; j < 4; j++) oacc[i][j] = 0.f;

    for (int kt = 0; kt <= qt; kt++) {
        cp_wait<0>();
        __syncthreads();
        if (kt < qt) load_kv((kt + 1) & 1, kt + 1);
        cp_commit();

        float* Kb = Ks + (kt & 1) * AQ;
        float* Vb = Vs + (kt & 1) * AV;

        // one-pass rna rounding of the landed tiles (swizzle is a bijection:
        // linear pass covers every element exactly once)
        if (kt == 0) round_smem(Qs, AQ, tid, 256);
        round_smem(Kb, AQ, tid, 256);
        round_smem(Vb, AV, tid, 256);
        __syncthreads();

        // ---- S = Q K^T (warp tile 16x32), cvt-free ----
        float sacc[4][4];
#pragma unroll
        for (int i = 0; i < 4; i++)
#pragma unroll
            for (int j = 0; j < 4; j++) sacc[i][j] = 0.f;

        {
            int r0 = wm * 16 + (lane >> 2);
            int swa = 4 * ((lane >> 2) & 7);
            const float* Aq0 = Qs + r0 * 192;
            const float* Aq8 = Qs + (r0 + 8) * 192;
#pragma unroll 4
            for (int k0 = 0; k0 < QKD; k0 += 8) {
                int k = k0 + (lane & 3);
                unsigned a[4];
                a[0] = fbits(Aq0[k ^ swa]);
                a[1] = fbits(Aq8[k ^ swa]);
                a[2] = fbits(Aq0[(k + 4) ^ swa]);
                a[3] = fbits(Aq8[(k + 4) ^ swa]);
#pragma unroll
                for (int nf = 0; nf < 4; nf++) {
                    const float* pb = Kb + (wn * 32 + nf * 8 + (lane >> 2)) * 192;
                    unsigned b[2] = { fbits(pb[k ^ swa]), fbits(pb[(k + 4) ^ swa]) };
                    mma_tf32(sacc[nf], a, b);
                }
            }
        }
#pragma unroll
        for (int nf = 0; nf < 4; nf++) {
            int r = wm * 16 + (lane >> 2);
            int c = wn * 32 + nf * 8 + 2 * (lane & 3);
            Ps[r * APP + c] = sacc[nf][0];
            Ps[r * APP + c + 1] = sacc[nf][1];
            Ps[(r + 8) * APP + c] = sacc[nf][2];
            Ps[(r + 8) * APP + c + 1] = sacc[nf][3];
        }
        __syncthreads();

        // ---- online softmax (scale in exponent); P stored tf32-rounded ----
        {
            int row = tid >> 2, sub = tid & 3;
            float* pr = Ps + row * APP + sub * 16;
            bool diag = (kt == qt);
            float v[16];
#pragma unroll
            for (int j = 0; j < 16; j++) {
                float x = pr[j];
                if (diag && (sub * 16 + j) > row) x = -1e30f;
                v[j] = x;
            }
            float mx = v[0];
#pragma unroll
            for (int j = 1; j < 16; j++) mx = fmaxf(mx, v[j]);
            mx = fmaxf(mx, __shfl_xor_sync(0xffffffffu, mx, 1));
            mx = fmaxf(mx, __shfl_xor_sync(0xffffffffu, mx, 2));
            float mo = m_s[row];
            float mn = fmaxf(mo, mx);
            float sum = 0.f;
#pragma unroll
            for (int j = 0; j < 16; j++) {
                float p = __expf((v[j] - mn) * SCALEF);
                sum += p;
                pr[j] = tf32r(p);
            }
            sum += __shfl_xor_sync(0xffffffffu, sum, 1);
            sum += __shfl_xor_sync(0xffffffffu, sum, 2);
            if (sub == 0) {
                float al = __expf((mo - mn) * SCALEF);
                al_s[row] = al;
                l_s[row] = l_s[row] * al + sum;
                m_s[row] = mn;
            }
        }
        __syncthreads();

        // ---- O = O*alpha + P V (warp tile 16x64), cvt-free ----
        {
            int r0 = wm * 16 + (lane >> 2);
            float al0 = al_s[r0], al1 = al_s[r0 + 8];
#pragma unroll
            for (int nf = 0; nf < 8; nf++) {
                oacc[nf][0] *= al0; oacc[nf][1] *= al0;
                oacc[nf][2] *= al1; oacc[nf][3] *= al1;
            }
            const float* Ap0 = Ps + r0 * APP + (lane & 3);
            int swv = 8 * (lane & 3);
#pragma unroll
            for (int k0 = 0; k0 < 64; k0 += 8) {
                unsigned a[4];
                a[0] = fbits(Ap0[k0]);
                a[1] = fbits(Ap0[k0 + 8 * APP]);
                a[2] = fbits(Ap0[k0 + 4]);
                a[3] = fbits(Ap0[k0 + 4 + 8 * APP]);
                int kr = k0 + (lane & 3);
                const float* Vr0 = Vb + kr * 128;
                const float* Vr4 = Vb + (kr + 4) * 128;
#pragma unroll
                for (int nf = 0; nf < 8; nf++) {
                    int col = wn * 64 + nf * 8 + (lane >> 2);
                    unsigned b[2] = { fbits(Vr0[col ^ swv]), fbits(Vr4[col ^ swv]) };
                    mma_tf32(oacc[nf], a, b);
                }
            }
        }
    }

    {
        int r0 = wm * 16 + (lane >> 2);
        float inv0 = 1.f / l_s[r0], inv1 = 1.f / l_s[r0 + 8];
        int t0 = qt * 64 + r0;
#pragma unroll
        for (int nf = 0; nf < 8; nf++) {
            int c = wn * 64 + nf * 8 + 2 * (lane & 3);
            float* y0 = y + (size_t)t0 * CC + h * DV + c;
            float* y1 = y + (size_t)(t0 + 8) * CC + h * DV + c;
            y0[0] = oacc[nf][0] * inv0;
            y0[1] = oacc[nf][1] * inv0;
            y1[0] = oacc[nf][2] * inv1;
            y1[1] = oacc[nf][3] * inv1;
        }
    }
}

// ---------------- launch ----------------
extern "C" void kernel_launch(void* const* d_in, const int* in_sizes, int n_in,
                              void* d_out, int out_size) {
    const float* x        = (const float*)d_in[0];
    const float* freqs    = (const float*)d_in[1];
    const float* wq_a     = (const float*)d_in[2];
    const float* bq_a     = (const float*)d_in[3];
    const float* q_norm_w = (const float*)d_in[4];
    const float* wq_b     = (const float*)d_in[5];
    const float* bq_b     = (const float*)d_in[6];
    const float* wkv_a    = (const float*)d_in[7];
    const float* bkv_a    = (const float*)d_in[8];
    const float* kv_norm_w= (const float*)d_in[9];
    const float* wkv_b    = (const float*)d_in[10];
    const float* bkv_b    = (const float*)d_in[11];
    const float* wo       = (const float*)d_in[12];
    const float* bo       = (const float*)d_in[13];
    float* out = (float*)d_out;

    float *qlat, *qbuf, *kvpe, *kvlat, *kvb, *ybuf;
    cudaGetSymbolAddress((void**)&qlat,  g_qlat);
    cudaGetSymbolAddress((void**)&qbuf,  g_q);
    cudaGetSymbolAddress((void**)&kvpe,  g_kvpe);
    cudaGetSymbolAddress((void**)&kvlat, g_kvlat);
    cudaGetSymbolAddress((void**)&kvb,   g_kvb);
    cudaGetSymbolAddress((void**)&ybuf,  g_y);

    cudaFuncSetAttribute(gemm_tc<8>, cudaFuncAttributeMaxDynamicSharedMemorySize, gsmem(8));
    cudaFuncSetAttribute(gemm_tc<4>, cudaFuncAttributeMaxDynamicSharedMemorySize, gsmem(4));
    cudaFuncSetAttribute(attn_tc,    cudaFuncAttributeMaxDynamicSharedMemorySize, ATTN_SMEM);

    // Q path
    gemm_tc<8><<<dim3(RQ / 128, TT / 128), 128, gsmem(8)>>>(x, wq_a, bq_a, qlat, CC);
    rmsnorm_kernel<<<TT, 256>>>(qlat, RQ, qlat, RQ, q_norm_w, RQ);
    gemm_tc<8><<<dim3((HH * QKD) / 128, TT / 128), 128, gsmem(8)>>>(qlat, wq_b, bq_b, qbuf, RQ);
    rope_q_kernel<<<(TT * HH * 32 + 255) / 256, 256>>>(freqs);

    // KV path
    gemm_tc<4><<<dim3((RKV + DR) / 64, TT / 128), 128, gsmem(4)>>>(x, wkv_a, bkv_a, kvpe, CC);
    rope_k_kernel<<<(TT * 32 + 255) / 256, 256>>>(freqs);
    rmsnorm_kernel<<<TT, 256>>>(kvpe, RKV + DR, kvlat, RKV, kv_norm_w, RKV);
    gemm_tc<8><<<dim3((HH * 256) / 128, TT / 128), 128, gsmem(8)>>>(kvlat, wkv_b, bkv_b, kvb, RKV);

    // Attention
    attn_tc<<<dim3(TT / 64, HH), 256, ATTN_SMEM>>>(qbuf, kvb, kvpe, ybuf);

    // Output projection
    gemm_tc<8><<<dim3(CC / 128, TT / 128), 128, gsmem(8)>>>(ybuf, wo, bo, out, CC);
}

// round 14
// speedup vs baseline: 1.0952x; 1.0952x over previous
#include <cuda_runtime.h>
#include <cstdint>
#include <math.h>

#define TT 2048
#define CC 2048
#define HH 16
#define DN 128
#define DR 64
#define DV 128
#define QKD 192
#define RQ 1536
#define RKV 512
#define EPSF 1e-6f
#define SCALEF 0.07216878364870323f  // 192^-0.5

// ---------------- scratch (device globals; no allocation allowed) ----------------
__device__ float g_qlat[TT * RQ];
__device__ float g_q[TT * HH * QKD];
__device__ float g_kvpe[TT * (RKV + DR)];
__device__ float g_kvlat[TT * RKV];
__device__ float g_kvb[TT * HH * (DN + DV)];
__device__ float g_y[TT * CC];

// ---------------- helpers ----------------
__device__ __forceinline__ float tf32r(float f) {
    unsigned u;
    asm("cvt.rna.tf32.f32 %0, %1;" : "=r"(u) : "f"(f));
    return __uint_as_float(u);
}
__device__ __forceinline__ unsigned fbits(float f) { return __float_as_uint(f); }
__device__ __forceinline__ unsigned ldt(const float* p) { return fbits(tf32r(*p)); }

__device__ __forceinline__ void mma_tf32(float c[4], const unsigned a[4], const unsigned b[2]) {
    asm volatile(
        "mma.sync.aligned.m16n8k8.row.col.f32.tf32.tf32.f32 "
        "{%0,%1,%2,%3}, {%4,%5,%6,%7}, {%8,%9}, {%0,%1,%2,%3};"
        : "+f"(c[0]), "+f"(c[1]), "+f"(c[2]), "+f"(c[3])
        : "r"(a[0]), "r"(a[1]), "r"(a[2]), "r"(a[3]), "r"(b[0]), "r"(b[1]));
}

__device__ __forceinline__ void cpa16(float* s, const float* g) {
    unsigned sa = (unsigned)__cvta_generic_to_shared(s);
    asm volatile("cp.async.cg.shared.global [%0], [%1], 16;" :: "r"(sa), "l"(g) : "memory");
}
__device__ __forceinline__ void cp_commit() { asm volatile("cp.async.commit_group;" ::: "memory"); }
template <int N>
__device__ __forceinline__ void cp_wait() { asm volatile("cp.async.wait_group %0;" :: "n"(N) : "memory"); }

// ---------------- tensor-core GEMM: C[M,N] = A[M,K] @ B[N,K]^T + bias ----------------
// Block 128 x (16*NF), 128 threads (4 warps, 2x2 grid), warp tile 64 x (8*NF).
// 3-stage cp.async pipeline; rna cvt at fragment-load time.
// RND: round epilogue outputs to tf32 (for buffers consumed raw by attention).
#define GPIT 36

template <int NF, bool RND>
__global__ void __launch_bounds__(128, 2) gemm_tc(
    const float* __restrict__ A, const float* __restrict__ B,
    const float* __restrict__ bias, float* __restrict__ Cm,
    int K)
{
    constexpr int BM = 128, BN = 16 * NF;
    constexpr int ASTAGE = BM * GPIT, BSTAGE = BN * GPIT;

    extern __shared__ float sh[];
    float* As = sh;
    float* Bs = sh + 3 * ASTAGE;

    int tid = threadIdx.x;
    int lane = tid & 31, warp = tid >> 5;
    int wm = warp >> 1, wn = warp & 1;
    int m0 = blockIdx.y * BM, n0 = blockIdx.x * BN;
    int N = gridDim.x * BN;

    auto load_stage = [&](int s, int k0) {
#pragma unroll
        for (int i = 0; i < (BM * 8) / 128; i++) {
            int idx = i * 128 + tid, r = idx >> 3, c = (idx & 7) << 2;
            cpa16(As + s * ASTAGE + r * GPIT + c, A + (size_t)(m0 + r) * K + k0 + c);
        }
#pragma unroll
        for (int i = 0; i < (BN * 8) / 128; i++) {
            int idx = i * 128 + tid, r = idx >> 3, c = (idx & 7) << 2;
            cpa16(Bs + s * BSTAGE + r * GPIT + c, B + (size_t)(n0 + r) * K + k0 + c);
        }
    };

    float acc[4][NF][4];
#pragma unroll
    for (int i = 0; i < 4; i++)
#pragma unroll
        for (int j = 0; j < NF; j++)
#pragma unroll
            for (int k = 0; k < 4; k++) acc[i][j][k] = 0.f;

    load_stage(0, 0); cp_commit();
    load_stage(1, 32); cp_commit();

    int nIter = K >> 5;
    for (int it = 0; it < nIter; it++) {
        cp_wait<1>();
        __syncthreads();
        if (it + 2 < nIter) load_stage((it + 2) % 3, (it + 2) << 5);
        cp_commit();

        const float* Ab = As + (it % 3) * ASTAGE;
        const float* Bb = Bs + (it % 3) * BSTAGE;
#pragma unroll
        for (int ks = 0; ks < 4; ks++) {
            int kidx = ks * 8 + (lane & 3);
            unsigned af[4][4], bf[NF][2];
            int arow = wm * 64 + (lane >> 2);
#pragma unroll
            for (int mf = 0; mf < 4; mf++) {
                const float* p = Ab + (arow + mf * 16) * GPIT + kidx;
                af[mf][0] = ldt(p);
                af[mf][1] = ldt(p + 8 * GPIT);
                af[mf][2] = ldt(p + 4);
                af[mf][3] = ldt(p + 8 * GPIT + 4);
            }
            int brow = wn * (NF * 8) + (lane >> 2);
#pragma unroll
            for (int nf = 0; nf < NF; nf++) {
                const float* p = Bb + (brow + nf * 8) * GPIT + kidx;
                bf[nf][0] = ldt(p);
                bf[nf][1] = ldt(p + 4);
            }
#pragma unroll
            for (int mf = 0; mf < 4; mf++)
#pragma unroll
                for (int nf = 0; nf < NF; nf++)
                    mma_tf32(acc[mf][nf], af[mf], bf[nf]);
        }
    }

#pragma unroll
    for (int mf = 0; mf < 4; mf++) {
        int row0 = m0 + wm * 64 + mf * 16 + (lane >> 2);
#pragma unroll
        for (int nf = 0; nf < NF; nf++) {
            int col = n0 + wn * (NF * 8) + nf * 8 + 2 * (lane & 3);
            float b0 = bias[col], b1 = bias[col + 1];
            float v00 = acc[mf][nf][0] + b0, v01 = acc[mf][nf][1] + b1;
            float v10 = acc[mf][nf][2] + b0, v11 = acc[mf][nf][3] + b1;
            if (RND) { v00 = tf32r(v00); v01 = tf32r(v01); v10 = tf32r(v10); v11 = tf32r(v11); }
            *(float2*)&Cm[(size_t)row0 * N + col] = make_float2(v00, v01);
            *(float2*)&Cm[(size_t)(row0 + 8) * N + col] = make_float2(v10, v11);
        }
    }
}

static inline int gsmem(int NF) { return 3 * (128 + 16 * NF) * GPIT * 4; }

// ---------------- RMSNorm (row-wise) ----------------
__global__ void __launch_bounds__(256) rmsnorm_kernel(
    const float* __restrict__ src, int srcStride,
    float* __restrict__ dst, int dstStride,
    const float* __restrict__ w, int cols)
{
    int row = blockIdx.x;
    const float* s = src + (size_t)row * srcStride;
    float* d = dst + (size_t)row * dstStride;
    float sum = 0.f;
    for (int i = threadIdx.x; i < cols; i += 256) { float v = s[i]; sum += v * v; }
    __shared__ float red[256];
    red[threadIdx.x] = sum;
    __syncthreads();
    for (int o = 128; o > 0; o >>= 1) {
        if (threadIdx.x < o) red[threadIdx.x] += red[threadIdx.x + o];
        __syncthreads();
    }
    float inv = rsqrtf(red[0] / (float)cols + EPSF);
    for (int i = threadIdx.x; i < cols; i += 256) d[i] = s[i] * inv * w[i];
}

// ---------------- RoPE (outputs tf32-rounded: feed attention raw-load path) ----------------
__global__ void rope_q_kernel(const float* __restrict__ freqs) {
    int idx = blockIdx.x * blockDim.x + threadIdx.x;
    if (idx >= TT * HH * 32) return;
    int i = idx & 31;
    int h = (idx >> 5) & 15;
    int t = idx >> 9;
    float f = freqs[t * 32 + i];
    float c = cosf(f), s = sinf(f);
    float* p = g_q + (size_t)t * (HH * QKD) + h * QKD + DN + 2 * i;
    float x0 = p[0], x1 = p[1];
    p[0] = tf32r(x0 * c - x1 * s);
    p[1] = tf32r(x0 * s + x1 * c);
}

__global__ void rope_k_kernel(const float* __restrict__ freqs) {
    int idx = blockIdx.x * blockDim.x + threadIdx.x;
    if (idx >= TT * 32) return;
    int i = idx & 31;
    int t = idx >> 5;
    float f = freqs[t * 32 + i];
    float c = cosf(f), s = sinf(f);
    float* p = g_kvpe + (size_t)t * (RKV + DR) + RKV + 2 * i;
    float x0 = p[0], x1 = p[1];
    p[0] = tf32r(x0 * c - x1 * s);
    p[1] = tf32r(x0 * s + x1 * c);
}

// ---------------- Flash attention (mma.sync tf32, cp.async double-buffered) ----------------
// Q/K/V arrive pre-rounded to tf32 -> hot loops are pure LDS + MMA (no cvt).
// Q fragments hoisted into registers once per CTA.
#define AQ (64 * 192)
#define AV (64 * 128)
#define APP 68
#define ATTN_FLOATS (3 * AQ + 2 * AV + 64 * APP + 192)
#define ATTN_SMEM (ATTN_FLOATS * 4)

__global__ void __launch_bounds__(256, 1) attn_tc(
    const float* __restrict__ q, const float* __restrict__ kvb,
    const float* __restrict__ kvpe, float* __restrict__ y)
{
    extern __shared__ float sm[];
    float* Qs = sm;
    float* Ks = sm + AQ;
    float* Vs = sm + 3 * AQ;
    float* Ps = sm + 3 * AQ + 2 * AV;
    float* m_s = Ps + 64 * APP;
    float* l_s = m_s + 64;
    float* al_s = l_s + 64;

    int h = blockIdx.y;
    int qt = gridDim.x - 1 - blockIdx.x;
    int tid = threadIdx.x, lane = tid & 31, warp = tid >> 5;
    int wm = warp >> 1, wn = warp & 1;

    int lr = tid >> 2;
    int lq = tid & 3;

    auto load_kv = [&](int buf, int kt2) {
        int t = kt2 * 64 + lr;
        const float* gk = kvb + (size_t)t * 4096 + h * 256;
        const float* gp = kvpe + (size_t)t * 576 + 512;
        float* Kb = Ks + buf * AQ + lr * 192;
        int sw = 4 * (lr & 7);
#pragma unroll
        for (int j = 0; j < 12; j++) {
            int c4 = lq * 12 + j;
            const float* src = (c4 < 32) ? (gk + 4 * c4) : (gp + 4 * (c4 - 32));
            cpa16(&Kb[(4 * c4) ^ sw], src);
        }
        float* Vb = Vs + buf * AV + lr * 128;
        int swv = 8 * (lr & 3);
#pragma unroll
        for (int j = 0; j < 8; j++) {
            int c4 = lq * 8 + j;
            cpa16(&Vb[(4 * c4) ^ swv], gk + 128 + 4 * c4);
        }
    };

    {
        const float* gq = q + (size_t)(qt * 64 + lr) * (HH * QKD) + h * QKD;
        float* Qr = Qs + lr * 192;
        int sw = 4 * (lr & 7);
#pragma unroll
        for (int j = 0; j < 12; j++) {
            int c4 = lq * 12 + j;
            cpa16(&Qr[(4 * c4) ^ sw], gq + 4 * c4);
        }
    }
    load_kv(0, 0);
    cp_commit();

    if (tid < 64) { m_s[tid] = -1e30f; l_s[tid] = 0.f; }

    float oacc[8][4];
#pragma unroll
    for (int i = 0; i < 8; i++)
#pragma unroll
        for (int j = 0; j < 4; j++) oacc[i][j] = 0.f;

    unsigned qf[24][4];  // hoisted Q fragments (constant over kt)

    int r0w = wm * 16 + (lane >> 2);
    int swa = 4 * ((lane >> 2) & 7);

    for (int kt = 0; kt <= qt; kt++) {
        cp_wait<0>();
        __syncthreads();
        if (kt < qt) load_kv((kt + 1) & 1, kt + 1);
        cp_commit();

        if (kt == 0) {
            const float* Aq0 = Qs + r0w * 192;
            const float* Aq8 = Qs + (r0w + 8) * 192;
#pragma unroll
            for (int s = 0; s < 24; s++) {
                int k = s * 8 + (lane & 3);
                qf[s][0] = fbits(Aq0[k ^ swa]);
                qf[s][1] = fbits(Aq8[k ^ swa]);
                qf[s][2] = fbits(Aq0[(k + 4) ^ swa]);
                qf[s][3] = fbits(Aq8[(k + 4) ^ swa]);
            }
        }

        const float* Kb = Ks + (kt & 1) * AQ;
        const float* Vb = Vs + (kt & 1) * AV;

        // ---- S = Q K^T (warp tile 16x32), cvt-free, Q in regs ----
        float sacc[4][4];
#pragma unroll
        for (int i = 0; i < 4; i++)
#pragma unroll
            for (int j = 0; j < 4; j++) sacc[i][j] = 0.f;

#pragma unroll 4
        for (int s = 0; s < 24; s++) {
            int k = s * 8 + (lane & 3);
#pragma unroll
            for (int nf = 0; nf < 4; nf++) {
                const float* pb = Kb + (wn * 32 + nf * 8 + (lane >> 2)) * 192;
                unsigned b[2] = { fbits(pb[k ^ swa]), fbits(pb[(k + 4) ^ swa]) };
                mma_tf32(sacc[nf], qf[s], b);
            }
        }
#pragma unroll
        for (int nf = 0; nf < 4; nf++) {
            int c = wn * 32 + nf * 8 + 2 * (lane & 3);
            Ps[r0w * APP + c] = sacc[nf][0];
            Ps[r0w * APP + c + 1] = sacc[nf][1];
            Ps[(r0w + 8) * APP + c] = sacc[nf][2];
            Ps[(r0w + 8) * APP + c + 1] = sacc[nf][3];
        }
        __syncthreads();

        // ---- online softmax (scale in exponent); P stored tf32-rounded ----
        {
            int row = tid >> 2, sub = tid & 3;
            float* pr = Ps + row * APP + sub * 16;
            bool diag = (kt == qt);
            float v[16];
#pragma unroll
            for (int j = 0; j < 16; j++) {
                float x = pr[j];
                if (diag && (sub * 16 + j) > row) x = -1e30f;
                v[j] = x;
            }
            float mx = v[0];
#pragma unroll
            for (int j = 1; j < 16; j++) mx = fmaxf(mx, v[j]);
            mx = fmaxf(mx, __shfl_xor_sync(0xffffffffu, mx, 1));
            mx = fmaxf(mx, __shfl_xor_sync(0xffffffffu, mx, 2));
            float mo = m_s[row];
            float mn = fmaxf(mo, mx);
            float sum = 0.f;
#pragma unroll
            for (int j = 0; j < 16; j++) {
                float p = __expf((v[j] - mn) * SCALEF);
                sum += p;
                pr[j] = tf32r(p);
            }
            sum += __shfl_xor_sync(0xffffffffu, sum, 1);
            sum += __shfl_xor_sync(0xffffffffu, sum, 2);
            if (sub == 0) {
                float al = __expf((mo - mn) * SCALEF);
                al_s[row] = al;
                l_s[row] = l_s[row] * al + sum;
                m_s[row] = mn;
            }
        }
        __syncthreads();

        // ---- O = O*alpha + P V (warp tile 16x64), cvt-free ----
        {
            float al0 = al_s[r0w], al1 = al_s[r0w + 8];
#pragma unroll
            for (int nf = 0; nf < 8; nf++) {
                oacc[nf][0] *= al0; oacc[nf][1] *= al0;
                oacc[nf][2] *= al1; oacc[nf][3] *= al1;
            }
            const float* Ap0 = Ps + r0w * APP + (lane & 3);
            int swv = 8 * (lane & 3);
#pragma unroll
            for (int k0 = 0; k0 < 64; k0 += 8) {
                unsigned a[4];
                a[0] = fbits(Ap0[k0]);
                a[1] = fbits(Ap0[k0 + 8 * APP]);
                a[2] = fbits(Ap0[k0 + 4]);
                a[3] = fbits(Ap0[k0 + 4 + 8 * APP]);
                int kr = k0 + (lane & 3);
                const float* Vr0 = Vb + kr * 128;
                const float* Vr4 = Vb + (kr + 4) * 128;
#pragma unroll
                for (int nf = 0; nf < 8; nf++) {
                    int col = wn * 64 + nf * 8 + (lane >> 2);
                    unsigned b[2] = { fbits(Vr0[col ^ swv]), fbits(Vr4[col ^ swv]) };
                    mma_tf32(oacc[nf], a, b);
                }
            }
        }
    }

    {
        float inv0 = 1.f / l_s[r0w], inv1 = 1.f / l_s[r0w + 8];
        int t0 = qt * 64 + r0w;
#pragma unroll
        for (int nf = 0; nf < 8; nf++) {
            int c = wn * 64 + nf * 8 + 2 * (lane & 3);
            float* y0 = y + (size_t)t0 * CC + h * DV + c;
            float* y1 = y + (size_t)(t0 + 8) * CC + h * DV + c;
            y0[0] = oacc[nf][0] * inv0;
            y0[1] = oacc[nf][1] * inv0;
            y1[0] = oacc[nf][2] * inv1;
            y1[1] = oacc[nf][3] * inv1;
        }
    }
}

// ---------------- launch ----------------
extern "C" void kernel_launch(void* const* d_in, const int* in_sizes, int n_in,
                              void* d_out, int out_size) {
    const float* x        = (const float*)d_in[0];
    const float* freqs    = (const float*)d_in[1];
    const float* wq_a     = (const float*)d_in[2];
    const float* bq_a     = (const float*)d_in[3];
    const float* q_norm_w = (const float*)d_in[4];
    const float* wq_b     = (const float*)d_in[5];
    const float* bq_b     = (const float*)d_in[6];
    const float* wkv_a    = (const float*)d_in[7];
    const float* bkv_a    = (const float*)d_in[8];
    const float* kv_norm_w= (const float*)d_in[9];
    const float* wkv_b    = (const float*)d_in[10];
    const float* bkv_b    = (const float*)d_in[11];
    const float* wo       = (const float*)d_in[12];
    const float* bo       = (const float*)d_in[13];
    float* out = (float*)d_out;

    float *qlat, *qbuf, *kvpe, *kvlat, *kvb, *ybuf;
    cudaGetSymbolAddress((void**)&qlat,  g_qlat);
    cudaGetSymbolAddress((void**)&qbuf,  g_q);
    cudaGetSymbolAddress((void**)&kvpe,  g_kvpe);
    cudaGetSymbolAddress((void**)&kvlat, g_kvlat);
    cudaGetSymbolAddress((void**)&kvb,   g_kvb);
    cudaGetSymbolAddress((void**)&ybuf,  g_y);

    cudaFuncSetAttribute((const void*)gemm_tc<8,false>, cudaFuncAttributeMaxDynamicSharedMemorySize, gsmem(8));
    cudaFuncSetAttribute((const void*)gemm_tc<8,true>,  cudaFuncAttributeMaxDynamicSharedMemorySize, gsmem(8));
    cudaFuncSetAttribute((const void*)gemm_tc<4,false>, cudaFuncAttributeMaxDynamicSharedMemorySize, gsmem(4));
    cudaFuncSetAttribute((const void*)attn_tc,          cudaFuncAttributeMaxDynamicSharedMemorySize, ATTN_SMEM);

    // Q path
    gemm_tc<8,false><<<dim3(RQ / 128, TT / 128), 128, gsmem(8)>>>(x, wq_a, bq_a, qlat, CC);
    rmsnorm_kernel<<<TT, 256>>>(qlat, RQ, qlat, RQ, q_norm_w, RQ);
    gemm_tc<8,true><<<dim3((HH * QKD) / 128, TT / 128), 128, gsmem(8)>>>(qlat, wq_b, bq_b, qbuf, RQ);
    rope_q_kernel<<<(TT * HH * 32 + 255) / 256, 256>>>(freqs);

    // KV path
    gemm_tc<4,false><<<dim3((RKV + DR) / 64, TT / 128), 128, gsmem(4)>>>(x, wkv_a, bkv_a, kvpe, CC);
    rope_k_kernel<<<(TT * 32 + 255) / 256, 256>>>(freqs);
    rmsnorm_kernel<<<TT, 256>>>(kvpe, RKV + DR, kvlat, RKV, kv_norm_w, RKV);
    gemm_tc<8,true><<<dim3((HH * 256) / 128, TT / 128), 128, gsmem(8)>>>(kvlat, wkv_b, bkv_b, kvb, RKV);

    // Attention
    attn_tc<<<dim3(TT / 64, HH), 256, ATTN_SMEM>>>(qbuf, kvb, kvpe, ybuf);

    // Output projection
    gemm_tc<8,false><<<dim3(CC / 128, TT / 128), 128, gsmem(8)>>>(ybuf, wo, bo, out, CC);
}

// round 15
// speedup vs baseline: 1.1263x; 1.0284x over previous
#include <cuda_runtime.h>
#include <cstdint>
#include <math.h>

#define TT 2048
#define CC 2048
#define HH 16
#define DN 128
#define DR 64
#define DV 128
#define QKD 192
#define RQ 1536
#define RKV 512
#define EPSF 1e-6f
#define SCALEF 0.07216878364870323f  // 192^-0.5

// ---------------- scratch (device globals; no allocation allowed) ----------------
__device__ float g_qlat[TT * RQ];
__device__ float g_q[TT * HH * QKD];
__device__ float g_kvpe[TT * (RKV + DR)];
__device__ float g_kvlat[TT * RKV];
__device__ float g_kvb[TT * HH * (DN + DV)];
__device__ float g_y[TT * CC];

// ---------------- helpers ----------------
__device__ __forceinline__ float tf32r(float f) {
    unsigned u;
    asm("cvt.rna.tf32.f32 %0, %1;" : "=r"(u) : "f"(f));
    return __uint_as_float(u);
}
__device__ __forceinline__ unsigned fbits(float f) { return __float_as_uint(f); }
__device__ __forceinline__ unsigned ldt(const float* p) { return fbits(tf32r(*p)); }

__device__ __forceinline__ void mma_tf32(float c[4], const unsigned a[4], const unsigned b[2]) {
    asm volatile(
        "mma.sync.aligned.m16n8k8.row.col.f32.tf32.tf32.f32 "
        "{%0,%1,%2,%3}, {%4,%5,%6,%7}, {%8,%9}, {%0,%1,%2,%3};"
        : "+f"(c[0]), "+f"(c[1]), "+f"(c[2]), "+f"(c[3])
        : "r"(a[0]), "r"(a[1]), "r"(a[2]), "r"(a[3]), "r"(b[0]), "r"(b[1]));
}

__device__ __forceinline__ void cpa16(float* s, const float* g) {
    unsigned sa = (unsigned)__cvta_generic_to_shared(s);
    asm volatile("cp.async.cg.shared.global [%0], [%1], 16;" :: "r"(sa), "l"(g) : "memory");
}
__device__ __forceinline__ void cp_commit() { asm volatile("cp.async.commit_group;" ::: "memory"); }
template <int N>
__device__ __forceinline__ void cp_wait() { asm volatile("cp.async.wait_group %0;" :: "n"(N) : "memory"); }

// ---------------- GEMM body: C[.,N] tile = A[M,K] @ B[N,K]^T + bias ----------------
// Block 128 x (16*NF), 128 threads (4 warps, 2x2), warp tile 64 x (8*NF).
// 3-stage cp.async pipeline; rna cvt at fragment-load time. (R14 body, verbatim.)
#define GPIT 36

template <int NF, bool RND>
__device__ __forceinline__ void gemm_body(
    const float* __restrict__ A, const float* __restrict__ B,
    const float* __restrict__ bias, float* __restrict__ Cm,
    int K, int N, int m0, int n0, float* sh)
{
    constexpr int BM = 128, BN = 16 * NF;
    constexpr int ASTAGE = BM * GPIT, BSTAGE = BN * GPIT;

    float* As = sh;
    float* Bs = sh + 3 * ASTAGE;

    int tid = threadIdx.x;
    int lane = tid & 31, warp = tid >> 5;
    int wm = warp >> 1, wn = warp & 1;

    auto load_stage = [&](int s, int k0) {
#pragma unroll
        for (int i = 0; i < (BM * 8) / 128; i++) {
            int idx = i * 128 + tid, r = idx >> 3, c = (idx & 7) << 2;
            cpa16(As + s * ASTAGE + r * GPIT + c, A + (size_t)(m0 + r) * K + k0 + c);
        }
#pragma unroll
        for (int i = 0; i < (BN * 8) / 128; i++) {
            int idx = i * 128 + tid, r = idx >> 3, c = (idx & 7) << 2;
            cpa16(Bs + s * BSTAGE + r * GPIT + c, B + (size_t)(n0 + r) * K + k0 + c);
        }
    };

    float acc[4][NF][4];
#pragma unroll
    for (int i = 0; i < 4; i++)
#pragma unroll
        for (int j = 0; j < NF; j++)
#pragma unroll
            for (int k = 0; k < 4; k++) acc[i][j][k] = 0.f;

    load_stage(0, 0); cp_commit();
    load_stage(1, 32); cp_commit();

    int nIter = K >> 5;
    for (int it = 0; it < nIter; it++) {
        cp_wait<1>();
        __syncthreads();
        if (it + 2 < nIter) load_stage((it + 2) % 3, (it + 2) << 5);
        cp_commit();

        const float* Ab = As + (it % 3) * ASTAGE;
        const float* Bb = Bs + (it % 3) * BSTAGE;
#pragma unroll
        for (int ks = 0; ks < 4; ks++) {
            int kidx = ks * 8 + (lane & 3);
            unsigned af[4][4], bf[NF][2];
            int arow = wm * 64 + (lane >> 2);
#pragma unroll
            for (int mf = 0; mf < 4; mf++) {
                const float* p = Ab + (arow + mf * 16) * GPIT + kidx;
                af[mf][0] = ldt(p);
                af[mf][1] = ldt(p + 8 * GPIT);
                af[mf][2] = ldt(p + 4);
                af[mf][3] = ldt(p + 8 * GPIT + 4);
            }
            int brow = wn * (NF * 8) + (lane >> 2);
#pragma unroll
            for (int nf = 0; nf < NF; nf++) {
                const float* p = Bb + (brow + nf * 8) * GPIT + kidx;
                bf[nf][0] = ldt(p);
                bf[nf][1] = ldt(p + 4);
            }
#pragma unroll
            for (int mf = 0; mf < 4; mf++)
#pragma unroll
                for (int nf = 0; nf < NF; nf++)
                    mma_tf32(acc[mf][nf], af[mf], bf[nf]);
        }
    }

#pragma unroll
    for (int mf = 0; mf < 4; mf++) {
        int row0 = m0 + wm * 64 + mf * 16 + (lane >> 2);
#pragma unroll
        for (int nf = 0; nf < NF; nf++) {
            int col = n0 + wn * (NF * 8) + nf * 8 + 2 * (lane & 3);
            float b0 = bias[col], b1 = bias[col + 1];
            float v00 = acc[mf][nf][0] + b0, v01 = acc[mf][nf][1] + b1;
            float v10 = acc[mf][nf][2] + b0, v11 = acc[mf][nf][3] + b1;
            if (RND) { v00 = tf32r(v00); v01 = tf32r(v01); v10 = tf32r(v10); v11 = tf32r(v11); }
            *(float2*)&Cm[(size_t)row0 * N + col] = make_float2(v00, v01);
            *(float2*)&Cm[(size_t)(row0 + 8) * N + col] = make_float2(v10, v11);
        }
    }
}

static inline int gsmem(int NF) { return 3 * (128 + 16 * NF) * GPIT * 4; }

// ---------------- merged A-projections: x @ {wq_a, wkv_a}^T (same A, same K) ----------------
// grid.x = 24 (qlat, N=1536) + 9 (kvpe, N=576) = 33, BN=64. 528 CTAs: fully packed.
__global__ void __launch_bounds__(128, 2) gemm_a_merged(
    const float* __restrict__ x,
    const float* __restrict__ wqa, const float* __restrict__ bqa, float* __restrict__ qlat,
    const float* __restrict__ wkva, const float* __restrict__ bkva, float* __restrict__ kvpe)
{
    extern __shared__ float sh[];
    int bx = blockIdx.x, m0 = blockIdx.y * 128;
    if (bx < 24)
        gemm_body<4, false>(x, wqa, bqa, qlat, CC, RQ, m0, bx * 64, sh);
    else
        gemm_body<4, false>(x, wkva, bkva, kvpe, CC, RKV + DR, m0, (bx - 24) * 64, sh);
}

// ---------------- merged B-projections: {qlat@wq_b^T (K=1536), kvlat@wkv_b^T (K=512)} ----------------
// grid.x = 24 (qbuf, N=3072) + 32 (kvb, N=4096) = 56, BN=128. Long-K blocks first.
__global__ void __launch_bounds__(128, 2) gemm_b_merged(
    const float* __restrict__ qlat, const float* __restrict__ wqb,
    const float* __restrict__ bqb, float* __restrict__ qbuf,
    const float* __restrict__ kvlat, const float* __restrict__ wkvb,
    const float* __restrict__ bkvb, float* __restrict__ kvb)
{
    extern __shared__ float sh[];
    int bx = blockIdx.x, m0 = blockIdx.y * 128;
    if (bx < 24)
        gemm_body<8, true>(qlat, wqb, bqb, qbuf, RQ, HH * QKD, m0, bx * 128, sh);
    else
        gemm_body<8, true>(kvlat, wkvb, bkvb, kvb, RKV, HH * (DN + DV), m0, (bx - 24) * 128, sh);
}

// ---------------- output projection ----------------
__global__ void __launch_bounds__(128, 2) gemm_wo(
    const float* __restrict__ y, const float* __restrict__ wo,
    const float* __restrict__ bo, float* __restrict__ out)
{
    extern __shared__ float sh[];
    gemm_body<8, false>(y, wo, bo, out, CC, CC, blockIdx.y * 128, blockIdx.x * 128, sh);
}

// ---------------- merged rmsnorm(q) + rmsnorm(kv) + rope_k ----------------
// blocks [0,2048): q rows; [2048,4096): kv rows (+ rope on pe columns).
__global__ void __launch_bounds__(256) rmsnorm_rope_merged(
    const float* __restrict__ freqs,
    const float* __restrict__ q_norm_w, const float* __restrict__ kv_norm_w)
{
    int b = blockIdx.x;
    bool isq = b < TT;
    int row = isq ? b : b - TT;
    const float* s = isq ? (g_qlat + (size_t)row * RQ) : (g_kvpe + (size_t)row * (RKV + DR));
    float* d = isq ? (g_qlat + (size_t)row * RQ) : (g_kvlat + (size_t)row * RKV);
    const float* w = isq ? q_norm_w : kv_norm_w;
    int cols = isq ? RQ : RKV;

    float sum = 0.f;
    for (int i = threadIdx.x; i < cols; i += 256) { float v = s[i]; sum += v * v; }
    __shared__ float red[256];
    red[threadIdx.x] = sum;
    __syncthreads();
    for (int o = 128; o > 0; o >>= 1) {
        if (threadIdx.x < o) red[threadIdx.x] += red[threadIdx.x + o];
        __syncthreads();
    }
    float inv = rsqrtf(red[0] / (float)cols + EPSF);
    for (int i = threadIdx.x; i < cols; i += 256) d[i] = s[i] * inv * w[i];

    // rope_k on kvpe[row, 512:576] (independent of the rmsnorm columns)
    if (!isq && threadIdx.x < 32) {
        int i = threadIdx.x;
        float f = freqs[row * 32 + i];
        float c = cosf(f), sn = sinf(f);
        float* p = g_kvpe + (size_t)row * (RKV + DR) + RKV + 2 * i;
        float x0 = p[0], x1 = p[1];
        p[0] = tf32r(x0 * c - x1 * sn);
        p[1] = tf32r(x0 * sn + x1 * c);
    }
}

// ---------------- RoPE for Q (outputs tf32-rounded) ----------------
__global__ void rope_q_kernel(const float* __restrict__ freqs) {
    int idx = blockIdx.x * blockDim.x + threadIdx.x;
    if (idx >= TT * HH * 32) return;
    int i = idx & 31;
    int h = (idx >> 5) & 15;
    int t = idx >> 9;
    float f = freqs[t * 32 + i];
    float c = cosf(f), s = sinf(f);
    float* p = g_q + (size_t)t * (HH * QKD) + h * QKD + DN + 2 * i;
    float x0 = p[0], x1 = p[1];
    p[0] = tf32r(x0 * c - x1 * s);
    p[1] = tf32r(x0 * s + x1 * c);
}

// ---------------- Flash attention (mma.sync tf32, cp.async double-buffered) ----------------
// Q/K/V arrive pre-rounded to tf32 -> hot loops are pure LDS + MMA.
// Q fragments hoisted into registers once per CTA. (R14 kernel, verbatim.)
#define AQ (64 * 192)
#define AV (64 * 128)
#define APP 68
#define ATTN_FLOATS (3 * AQ + 2 * AV + 64 * APP + 192)
#define ATTN_SMEM (ATTN_FLOATS * 4)

__global__ void __launch_bounds__(256, 1) attn_tc(
    const float* __restrict__ q, const float* __restrict__ kvb,
    const float* __restrict__ kvpe, float* __restrict__ y)
{
    extern __shared__ float sm[];
    float* Qs = sm;
    float* Ks = sm + AQ;
    float* Vs = sm + 3 * AQ;
    float* Ps = sm + 3 * AQ + 2 * AV;
    float* m_s = Ps + 64 * APP;
    float* l_s = m_s + 64;
    float* al_s = l_s + 64;

    int h = blockIdx.y;
    int qt = gridDim.x - 1 - blockIdx.x;
    int tid = threadIdx.x, lane = tid & 31, warp = tid >> 5;
    int wm = warp >> 1, wn = warp & 1;

    int lr = tid >> 2;
    int lq = tid & 3;

    auto load_kv = [&](int buf, int kt2) {
        int t = kt2 * 64 + lr;
        const float* gk = kvb + (size_t)t * 4096 + h * 256;
        const float* gp = kvpe + (size_t)t * 576 + 512;
        float* Kb = Ks + buf * AQ + lr * 192;
        int sw = 4 * (lr & 7);
#pragma unroll
        for (int j = 0; j < 12; j++) {
            int c4 = lq * 12 + j;
            const float* src = (c4 < 32) ? (gk + 4 * c4) : (gp + 4 * (c4 - 32));
            cpa16(&Kb[(4 * c4) ^ sw], src);
        }
        float* Vb = Vs + buf * AV + lr * 128;
        int swv = 8 * (lr & 3);
#pragma unroll
        for (int j = 0; j < 8; j++) {
            int c4 = lq * 8 + j;
            cpa16(&Vb[(4 * c4) ^ swv], gk + 128 + 4 * c4);
        }
    };

    {
        const float* gq = q + (size_t)(qt * 64 + lr) * (HH * QKD) + h * QKD;
        float* Qr = Qs + lr * 192;
        int sw = 4 * (lr & 7);
#pragma unroll
        for (int j = 0; j < 12; j++) {
            int c4 = lq * 12 + j;
            cpa16(&Qr[(4 * c4) ^ sw], gq + 4 * c4);
        }
    }
    load_kv(0, 0);
    cp_commit();

    if (tid < 64) { m_s[tid] = -1e30f; l_s[tid] = 0.f; }

    float oacc[8][4];
#pragma unroll
    for (int i = 0; i < 8; i++)
#pragma unroll
        for (int j = 0; j < 4; j++) oacc[i][j] = 0.f;

    unsigned qf[24][4];

    int r0w = wm * 16 + (lane >> 2);
    int swa = 4 * ((lane >> 2) & 7);

    for (int kt = 0; kt <= qt; kt++) {
        cp_wait<0>();
        __syncthreads();
        if (kt < qt) load_kv((kt + 1) & 1, kt + 1);
        cp_commit();

        if (kt == 0) {
            const float* Aq0 = Qs + r0w * 192;
            const float* Aq8 = Qs + (r0w + 8) * 192;
#pragma unroll
            for (int s = 0; s < 24; s++) {
                int k = s * 8 + (lane & 3);
                qf[s][0] = fbits(Aq0[k ^ swa]);
                qf[s][1] = fbits(Aq8[k ^ swa]);
                qf[s][2] = fbits(Aq0[(k + 4) ^ swa]);
                qf[s][3] = fbits(Aq8[(k + 4) ^ swa]);
            }
        }

        const float* Kb = Ks + (kt & 1) * AQ;
        const float* Vb = Vs + (kt & 1) * AV;

        float sacc[4][4];
#pragma unroll
        for (int i = 0; i < 4; i++)
#pragma unroll
            for (int j = 0; j < 4; j++) sacc[i][j] = 0.f;

#pragma unroll 4
        for (int s = 0; s < 24; s++) {
            int k = s * 8 + (lane & 3);
#pragma unroll
            for (int nf = 0; nf < 4; nf++) {
                const float* pb = Kb + (wn * 32 + nf * 8 + (lane >> 2)) * 192;
                unsigned b[2] = { fbits(pb[k ^ swa]), fbits(pb[(k + 4) ^ swa]) };
                mma_tf32(sacc[nf], qf[s], b);
            }
        }
#pragma unroll
        for (int nf = 0; nf < 4; nf++) {
            int c = wn * 32 + nf * 8 + 2 * (lane & 3);
            Ps[r0w * APP + c] = sacc[nf][0];
            Ps[r0w * APP + c + 1] = sacc[nf][1];
            Ps[(r0w + 8) * APP + c] = sacc[nf][2];
            Ps[(r0w + 8) * APP + c + 1] = sacc[nf][3];
        }
        __syncthreads();

        {
            int row = tid >> 2, sub = tid & 3;
            float* pr = Ps + row * APP + sub * 16;
            bool diag = (kt == qt);
            float v[16];
#pragma unroll
            for (int j = 0; j < 16; j++) {
                float x = pr[j];
                if (diag && (sub * 16 + j) > row) x = -1e30f;
                v[j] = x;
            }
            float mx = v[0];
#pragma unroll
            for (int j = 1; j < 16; j++) mx = fmaxf(mx, v[j]);
            mx = fmaxf(mx, __shfl_xor_sync(0xffffffffu, mx, 1));
            mx = fmaxf(mx, __shfl_xor_sync(0xffffffffu, mx, 2));
            float mo = m_s[row];
            float mn = fmaxf(mo, mx);
            float sum = 0.f;
#pragma unroll
            for (int j = 0; j < 16; j++) {
                float p = __expf((v[j] - mn) * SCALEF);
                sum += p;
                pr[j] = tf32r(p);
            }
            sum += __shfl_xor_sync(0xffffffffu, sum, 1);
            sum += __shfl_xor_sync(0xffffffffu, sum, 2);
            if (sub == 0) {
                float al = __expf((mo - mn) * SCALEF);
                al_s[row] = al;
                l_s[row] = l_s[row] * al + sum;
                m_s[row] = mn;
            }
        }
        __syncthreads();

        {
            float al0 = al_s[r0w], al1 = al_s[r0w + 8];
#pragma unroll
            for (int nf = 0; nf < 8; nf++) {
                oacc[nf][0] *= al0; oacc[nf][1] *= al0;
                oacc[nf][2] *= al1; oacc[nf][3] *= al1;
            }
            const float* Ap0 = Ps + r0w * APP + (lane & 3);
            int swv = 8 * (lane & 3);
#pragma unroll
            for (int k0 = 0; k0 < 64; k0 += 8) {
                unsigned a[4];
                a[0] = fbits(Ap0[k0]);
                a[1] = fbits(Ap0[k0 + 8 * APP]);
                a[2] = fbits(Ap0[k0 + 4]);
                a[3] = fbits(Ap0[k0 + 4 + 8 * APP]);
                int kr = k0 + (lane & 3);
                const float* Vr0 = Vb + kr * 128;
                const float* Vr4 = Vb + (kr + 4) * 128;
#pragma unroll
                for (int nf = 0; nf < 8; nf++) {
                    int col = wn * 64 + nf * 8 + (lane >> 2);
                    unsigned b[2] = { fbits(Vr0[col ^ swv]), fbits(Vr4[col ^ swv]) };
                    mma_tf32(oacc[nf], a, b);
                }
            }
        }
    }

    {
        float inv0 = 1.f / l_s[r0w], inv1 = 1.f / l_s[r0w + 8];
        int t0 = qt * 64 + r0w;
#pragma unroll
        for (int nf = 0; nf < 8; nf++) {
            int c = wn * 64 + nf * 8 + 2 * (lane & 3);
            float* y0 = y + (size_t)t0 * CC + h * DV + c;
            float* y1 = y + (size_t)(t0 + 8) * CC + h * DV + c;
            y0[0] = oacc[nf][0] * inv0;
            y0[1] = oacc[nf][1] * inv0;
            y1[0] = oacc[nf][2] * inv1;
            y1[1] = oacc[nf][3] * inv1;
        }
    }
}

// ---------------- launch ----------------
extern "C" void kernel_launch(void* const* d_in, const int* in_sizes, int n_in,
                              void* d_out, int out_size) {
    const float* x        = (const float*)d_in[0];
    const float* freqs    = (const float*)d_in[1];
    const float* wq_a     = (const float*)d_in[2];
    const float* bq_a     = (const float*)d_in[3];
    const float* q_norm_w = (const float*)d_in[4];
    const float* wq_b     = (const float*)d_in[5];
    const float* bq_b     = (const float*)d_in[6];
    const float* wkv_a    = (const float*)d_in[7];
    const float* bkv_a    = (const float*)d_in[8];
    const float* kv_norm_w= (const float*)d_in[9];
    const float* wkv_b    = (const float*)d_in[10];
    const float* bkv_b    = (const float*)d_in[11];
    const float* wo       = (const float*)d_in[12];
    const float* bo       = (const float*)d_in[13];
    float* out = (float*)d_out;

    float *qlat, *qbuf, *kvpe, *kvlat, *kvb, *ybuf;
    cudaGetSymbolAddress((void**)&qlat,  g_qlat);
    cudaGetSymbolAddress((void**)&qbuf,  g_q);
    cudaGetSymbolAddress((void**)&kvpe,  g_kvpe);
    cudaGetSymbolAddress((void**)&kvlat, g_kvlat);
    cudaGetSymbolAddress((void**)&kvb,   g_kvb);
    cudaGetSymbolAddress((void**)&ybuf,  g_y);

    cudaFuncSetAttribute((const void*)gemm_a_merged, cudaFuncAttributeMaxDynamicSharedMemorySize, gsmem(4));
    cudaFuncSetAttribute((const void*)gemm_b_merged, cudaFuncAttributeMaxDynamicSharedMemorySize, gsmem(8));
    cudaFuncSetAttribute((const void*)gemm_wo,       cudaFuncAttributeMaxDynamicSharedMemorySize, gsmem(8));
    cudaFuncSetAttribute((const void*)attn_tc,       cudaFuncAttributeMaxDynamicSharedMemorySize, ATTN_SMEM);

    // 1. both A-projections, one packed launch
    gemm_a_merged<<<dim3(33, TT / 128), 128, gsmem(4)>>>(x, wq_a, bq_a, qlat, wkv_a, bkv_a, kvpe);

    // 2. both rmsnorms + rope_k, one launch
    rmsnorm_rope_merged<<<2 * TT, 256>>>(freqs, q_norm_w, kv_norm_w);

    // 3. both B-projections, one packed launch
    gemm_b_merged<<<dim3(56, TT / 128), 128, gsmem(8)>>>(qlat, wq_b, bq_b, qbuf, kvlat, wkv_b, bkv_b, kvb);

    // 4. rope on q
    rope_q_kernel<<<(TT * HH * 32 + 255) / 256, 256>>>(freqs);

    // 5. attention
    attn_tc<<<dim3(TT / 64, HH), 256, ATTN_SMEM>>>(qbuf, kvb, kvpe, ybuf);

    // 6. output projection
    gemm_wo<<<dim3(CC / 128, TT / 128), 128, gsmem(8)>>>(ybuf, wo, bo, out);
}

// round 17
// speedup vs baseline: 1.5072x; 1.3382x over previous
#include <cuda_runtime.h>
#include <cuda_fp16.h>
#include <cstdint>
#include <math.h>

#define TT 2048
#define CC 2048
#define HH 16
#define DN 128
#define DR 64
#define DV 128
#define QKD 192
#define RQ 1536
#define RKV 512
#define EPSF 1e-6f
#define SCALEF 0.07216878364870323f  // 192^-0.5

// ---------------- scratch (device globals; no allocation allowed) ----------------
__device__ float  g_qlat[TT * RQ];          // gemm_a out (fp32)
__device__ float  g_q[TT * HH * QKD];       // qbuf (fp32, tf32-rounded)
__device__ float  g_kvpe[TT * (RKV + DR)];  // gemm_a out (fp32)
__device__ float  g_kvb[TT * HH * (DN + DV)]; // (fp32, tf32-rounded)
__device__ __half g_qlat_h[TT * RQ];        // rmsnorm out (fp16)
__device__ __half g_kvlat_h[TT * RKV];      // rmsnorm out (fp16)
__device__ __half g_yh[TT * CC];            // attention out (fp16)
// fp16 copies of inputs
__device__ __half g_hx[TT * CC];
__device__ __half g_hwqa[RQ * CC];
__device__ __half g_hwqb[HH * QKD * RQ];
__device__ __half g_hwkva[(RKV + DR) * CC];
__device__ __half g_hwkvb[HH * (DN + DV) * RKV];
__device__ __half g_hwo[CC * CC];

// ---------------- helpers ----------------
__device__ __forceinline__ float tf32r(float f) {
    unsigned u;
    asm("cvt.rna.tf32.f32 %0, %1;" : "=r"(u) : "f"(f));
    return __uint_as_float(u);
}
__device__ __forceinline__ unsigned fbits(float f) { return __float_as_uint(f); }

__device__ __forceinline__ void mma_tf32(float c[4], const unsigned a[4], const unsigned b[2]) {
    asm volatile(
        "mma.sync.aligned.m16n8k8.row.col.f32.tf32.tf32.f32 "
        "{%0,%1,%2,%3}, {%4,%5,%6,%7}, {%8,%9}, {%0,%1,%2,%3};"
        : "+f"(c[0]), "+f"(c[1]), "+f"(c[2]), "+f"(c[3])
        : "r"(a[0]), "r"(a[1]), "r"(a[2]), "r"(a[3]), "r"(b[0]), "r"(b[1]));
}
__device__ __forceinline__ void mma_f16(float c[4], const unsigned a[4], const unsigned b[2]) {
    asm volatile(
        "mma.sync.aligned.m16n8k16.row.col.f32.f16.f16.f32 "
        "{%0,%1,%2,%3}, {%4,%5,%6,%7}, {%8,%9}, {%0,%1,%2,%3};"
        : "+f"(c[0]), "+f"(c[1]), "+f"(c[2]), "+f"(c[3])
        : "r"(a[0]), "r"(a[1]), "r"(a[2]), "r"(a[3]), "r"(b[0]), "r"(b[1]));
}

__device__ __forceinline__ void cpa16(float* s, const float* g) {
    unsigned sa = (unsigned)__cvta_generic_to_shared(s);
    asm volatile("cp.async.cg.shared.global [%0], [%1], 16;" :: "r"(sa), "l"(g) : "memory");
}
__device__ __forceinline__ void cpa16h(__half* s, const __half* g) {
    unsigned sa = (unsigned)__cvta_generic_to_shared(s);
    asm volatile("cp.async.cg.shared.global [%0], [%1], 16;" :: "r"(sa), "l"(g) : "memory");
}
__device__ __forceinline__ void cp_commit() { asm volatile("cp.async.commit_group;" ::: "memory"); }
template <int N>
__device__ __forceinline__ void cp_wait() { asm volatile("cp.async.wait_group %0;" :: "n"(N) : "memory"); }

// ---------------- fp32 -> fp16 conversion pass (x + 5 weights) ----------------
struct CSeg { const float* s; __half* d; unsigned n4; };
struct C6 { CSeg g[6]; };

__global__ void __launch_bounds__(256) conv_all(C6 P) {
    unsigned i0 = blockIdx.x * blockDim.x + threadIdx.x;
    unsigned stride = gridDim.x * blockDim.x;
#pragma unroll
    for (int k = 0; k < 6; k++) {
        const float4* src = (const float4*)P.g[k].s;
        __half2* dst = (__half2*)P.g[k].d;
        unsigned n4 = P.g[k].n4;
        for (unsigned i = i0; i < n4; i += 4 * stride) {
            // up to 4 independent float4s in flight for MLP
            float4 v0, v1, v2, v3;
            unsigned i1 = i + stride, i2 = i + 2 * stride, i3 = i + 3 * stride;
            v0 = src[i];
            if (i1 < n4) v1 = src[i1];
            if (i2 < n4) v2 = src[i2];
            if (i3 < n4) v3 = src[i3];
            dst[2 * i]     = __floats2half2_rn(v0.x, v0.y);
            dst[2 * i + 1] = __floats2half2_rn(v0.z, v0.w);
            if (i1 < n4) { dst[2*i1] = __floats2half2_rn(v1.x, v1.y); dst[2*i1+1] = __floats2half2_rn(v1.z, v1.w); }
            if (i2 < n4) { dst[2*i2] = __floats2half2_rn(v2.x, v2.y); dst[2*i2+1] = __floats2half2_rn(v2.z, v2.w); }
            if (i3 < n4) { dst[2*i3] = __floats2half2_rn(v3.x, v3.y); dst[2*i3+1] = __floats2half2_rn(v3.z, v3.w); }
        }
    }
}

// ---------------- fp16 tensor-core GEMM body: C[.,N] = A[M,K]h @ B[N,K]h^T + bias ----------------
// Block 128 x (16*NF), 128 threads (4 warps, 2x2), warp tile 64 x (8*NF).
// BK=64, 3-stage cp.async pipeline, smem fp16 pitch 72 halves (bank r*4+c, conflict-free).
#define HPIT 72   // halves per row (64 + 8 pad); 36 b32

template <int NF, bool RND>
__device__ __forceinline__ void gemm_h_body(
    const __half* __restrict__ A, const __half* __restrict__ B,
    const float* __restrict__ bias, float* __restrict__ Cm,
    int K, int N, int m0, int n0, __half* sh)
{
    constexpr int BM = 128, BN = 16 * NF;
    constexpr int AST = BM * HPIT, BST = BN * HPIT;  // halves per stage

    __half* As = sh;
    __half* Bs = sh + 3 * AST;

    int tid = threadIdx.x;
    int lane = tid & 31, warp = tid >> 5;
    int wm = warp >> 1, wn = warp & 1;

    auto load_stage = [&](int s, int k0) {
#pragma unroll
        for (int i = 0; i < (BM * 8) / 128; i++) {
            int idx = i * 128 + tid, r = idx >> 3, ch = idx & 7;
            cpa16h(As + s * AST + r * HPIT + ch * 8, A + (size_t)(m0 + r) * K + k0 + ch * 8);
        }
#pragma unroll
        for (int i = 0; i < (BN * 8) / 128; i++) {
            int idx = i * 128 + tid, r = idx >> 3, ch = idx & 7;
            cpa16h(Bs + s * BST + r * HPIT + ch * 8, B + (size_t)(n0 + r) * K + k0 + ch * 8);
        }
    };

    float acc[4][NF][4];
#pragma unroll
    for (int i = 0; i < 4; i++)
#pragma unroll
        for (int j = 0; j < NF; j++)
#pragma unroll
            for (int k = 0; k < 4; k++) acc[i][j][k] = 0.f;

    load_stage(0, 0);  cp_commit();
    load_stage(1, 64); cp_commit();

    int nIter = K >> 6;
    for (int it = 0; it < nIter; it++) {
        cp_wait<1>();
        __syncthreads();
        if (it + 2 < nIter) load_stage((it + 2) % 3, (it + 2) << 6);
        cp_commit();

        const unsigned* Ab = (const unsigned*)(As + (it % 3) * AST);  // b32 view, pitch 36
        const unsigned* Bb = (const unsigned*)(Bs + (it % 3) * BST);
#pragma unroll
        for (int ks = 0; ks < 4; ks++) {
            int kb = ks * 8 + (lane & 3);   // b32 column within row
            unsigned af[4][4], bf[NF][2];
            int arow = wm * 64 + (lane >> 2);
#pragma unroll
            for (int mf = 0; mf < 4; mf++) {
                int idx = (arow + mf * 16) * 36 + kb;
                af[mf][0] = Ab[idx];
                af[mf][1] = Ab[idx + 8 * 36];
                af[mf][2] = Ab[idx + 4];
                af[mf][3] = Ab[idx + 8 * 36 + 4];
            }
            int brow = wn * (NF * 8) + (lane >> 2);
#pragma unroll
            for (int nf = 0; nf < NF; nf++) {
                int idx = (brow + nf * 8) * 36 + kb;
                bf[nf][0] = Bb[idx];
                bf[nf][1] = Bb[idx + 4];
            }
#pragma unroll
            for (int mf = 0; mf < 4; mf++)
#pragma unroll
                for (int nf = 0; nf < NF; nf++)
                    mma_f16(acc[mf][nf], af[mf], bf[nf]);
        }
    }

#pragma unroll
    for (int mf = 0; mf < 4; mf++) {
        int row0 = m0 + wm * 64 + mf * 16 + (lane >> 2);
#pragma unroll
        for (int nf = 0; nf < NF; nf++) {
            int col = n0 + wn * (NF * 8) + nf * 8 + 2 * (lane & 3);
            float b0 = bias[col], b1 = bias[col + 1];
            float v00 = acc[mf][nf][0] + b0, v01 = acc[mf][nf][1] + b1;
            float v10 = acc[mf][nf][2] + b0, v11 = acc[mf][nf][3] + b1;
            if (RND) { v00 = tf32r(v00); v01 = tf32r(v01); v10 = tf32r(v10); v11 = tf32r(v11); }
            *(float2*)&Cm[(size_t)row0 * N + col] = make_float2(v00, v01);
            *(float2*)&Cm[(size_t)(row0 + 8) * N + col] = make_float2(v10, v11);
        }
    }
}

static inline int gsmemh(int NF) { return 3 * (128 + 16 * NF) * HPIT * 2; }

// ---------------- merged A-projections ----------------
__global__ void __launch_bounds__(128, 2) gemm_a_merged(
    const __half* __restrict__ x,
    const __half* __restrict__ wqa, const float* __restrict__ bqa, float* __restrict__ qlat,
    const __half* __restrict__ wkva, const float* __restrict__ bkva, float* __restrict__ kvpe)
{
    extern __shared__ char shc[];
    __half* sh = (__half*)shc;
    int bx = blockIdx.x, m0 = blockIdx.y * 128;
    if (bx < 24)
        gemm_h_body<4, false>(x, wqa, bqa, qlat, CC, RQ, m0, bx * 64, sh);
    else
        gemm_h_body<4, false>(x, wkva, bkva, kvpe, CC, RKV + DR, m0, (bx - 24) * 64, sh);
}

// ---------------- merged B-projections ----------------
__global__ void __launch_bounds__(128, 2) gemm_b_merged(
    const __half* __restrict__ qlat, const __half* __restrict__ wqb,
    const float* __restrict__ bqb, float* __restrict__ qbuf,
    const __half* __restrict__ kvlat, const __half* __restrict__ wkvb,
    const float* __restrict__ bkvb, float* __restrict__ kvb)
{
    extern __shared__ char shc[];
    __half* sh = (__half*)shc;
    int bx = blockIdx.x, m0 = blockIdx.y * 128;
    if (bx < 24)
        gemm_h_body<8, true>(qlat, wqb, bqb, qbuf, RQ, HH * QKD, m0, bx * 128, sh);
    else
        gemm_h_body<8, true>(kvlat, wkvb, bkvb, kvb, RKV, HH * (DN + DV), m0, (bx - 24) * 128, sh);
}

// ---------------- output projection ----------------
__global__ void __launch_bounds__(128, 2) gemm_wo(
    const __half* __restrict__ y, const __half* __restrict__ wo,
    const float* __restrict__ bo, float* __restrict__ out)
{
    extern __shared__ char shc[];
    __half* sh = (__half*)shc;
    gemm_h_body<8, false>(y, wo, bo, out, CC, CC, blockIdx.y * 128, blockIdx.x * 128, sh);
}

// ---------------- merged rmsnorm(q) + rmsnorm(kv) + rope_k; outputs fp16 ----------------
__global__ void __launch_bounds__(256) rmsnorm_rope_merged(
    const float* __restrict__ freqs,
    const float* __restrict__ q_norm_w, const float* __restrict__ kv_norm_w)
{
    int b = blockIdx.x;
    bool isq = b < TT;
    int row = isq ? b : b - TT;
    const float* s = isq ? (g_qlat + (size_t)row * RQ) : (g_kvpe + (size_t)row * (RKV + DR));
    __half* d = isq ? (g_qlat_h + (size_t)row * RQ) : (g_kvlat_h + (size_t)row * RKV);
    const float* w = isq ? q_norm_w : kv_norm_w;
    int cols = isq ? RQ : RKV;

    float sum = 0.f;
    for (int i = threadIdx.x; i < cols; i += 256) { float v = s[i]; sum += v * v; }
    __shared__ float red[256];
    red[threadIdx.x] = sum;
    __syncthreads();
    for (int o = 128; o > 0; o >>= 1) {
        if (threadIdx.x < o) red[threadIdx.x] += red[threadIdx.x + o];
        __syncthreads();
    }
    float inv = rsqrtf(red[0] / (float)cols + EPSF);
    for (int i = threadIdx.x; i < cols; i += 256) d[i] = __float2half(s[i] * inv * w[i]);

    // rope_k on kvpe[row, 512:576] (fp32, tf32-rounded for attention)
    if (!isq && threadIdx.x < 32) {
        int i = threadIdx.x;
        float f = freqs[row * 32 + i];
        float c = cosf(f), sn = sinf(f);
        float* p = g_kvpe + (size_t)row * (RKV + DR) + RKV + 2 * i;
        float x0 = p[0], x1 = p[1];
        p[0] = tf32r(x0 * c - x1 * sn);
        p[1] = tf32r(x0 * sn + x1 * c);
    }
}

// ---------------- RoPE for Q (fp32, tf32-rounded) ----------------
__global__ void rope_q_kernel(const float* __restrict__ freqs) {
    int idx = blockIdx.x * blockDim.x + threadIdx.x;
    if (idx >= TT * HH * 32) return;
    int i = idx & 31;
    int h = (idx >> 5) & 15;
    int t = idx >> 9;
    float f = freqs[t * 32 + i];
    float c = cosf(f), s = sinf(f);
    float* p = g_q + (size_t)t * (HH * QKD) + h * QKD + DN + 2 * i;
    float x0 = p[0], x1 = p[1];
    p[0] = tf32r(x0 * c - x1 * s);
    p[1] = tf32r(x0 * s + x1 * c);
}

// ---------------- Flash attention (tf32 mma, unchanged R15 except fp16 epilogue) ----------------
#define AQ (64 * 192)
#define AV (64 * 128)
#define APP 68
#define ATTN_FLOATS (3 * AQ + 2 * AV + 64 * APP + 192)
#define ATTN_SMEM (ATTN_FLOATS * 4)

__global__ void __launch_bounds__(256, 1) attn_tc(
    const float* __restrict__ q, const float* __restrict__ kvb,
    const float* __restrict__ kvpe, __half* __restrict__ y)
{
    extern __shared__ float sm[];
    float* Qs = sm;
    float* Ks = sm + AQ;
    float* Vs = sm + 3 * AQ;
    float* Ps = sm + 3 * AQ + 2 * AV;
    float* m_s = Ps + 64 * APP;
    float* l_s = m_s + 64;
    float* al_s = l_s + 64;

    int h = blockIdx.y;
    int qt = gridDim.x - 1 - blockIdx.x;
    int tid = threadIdx.x, lane = tid & 31, warp = tid >> 5;
    int wm = warp >> 1, wn = warp & 1;

    int lr = tid >> 2;
    int lq = tid & 3;

    auto load_kv = [&](int buf, int kt2) {
        int t = kt2 * 64 + lr;
        const float* gk = kvb + (size_t)t * 4096 + h * 256;
        const float* gp = kvpe + (size_t)t * 576 + 512;
        float* Kb = Ks + buf * AQ + lr * 192;
        int sw = 4 * (lr & 7);
#pragma unroll
        for (int j = 0; j < 12; j++) {
            int c4 = lq * 12 + j;
            const float* src = (c4 < 32) ? (gk + 4 * c4) : (gp + 4 * (c4 - 32));
            cpa16(&Kb[(4 * c4) ^ sw], src);
        }
        float* Vb = Vs + buf * AV + lr * 128;
        int swv = 8 * (lr & 3);
#pragma unroll
        for (int j = 0; j < 8; j++) {
            int c4 = lq * 8 + j;
            cpa16(&Vb[(4 * c4) ^ swv], gk + 128 + 4 * c4);
        }
    };

    {
        const float* gq = q + (size_t)(qt * 64 + lr) * (HH * QKD) + h * QKD;
        float* Qr = Qs + lr * 192;
        int sw = 4 * (lr & 7);
#pragma unroll
        for (int j = 0; j < 12; j++) {
            int c4 = lq * 12 + j;
            cpa16(&Qr[(4 * c4) ^ sw], gq + 4 * c4);
        }
    }
    load_kv(0, 0);
    cp_commit();

    if (tid < 64) { m_s[tid] = -1e30f; l_s[tid] = 0.f; }

    float oacc[8][4];
#pragma unroll
    for (int i = 0; i < 8; i++)
#pragma unroll
        for (int j = 0; j < 4; j++) oacc[i][j] = 0.f;

    unsigned qf[24][4];

    int r0w = wm * 16 + (lane >> 2);
    int swa = 4 * ((lane >> 2) & 7);

    for (int kt = 0; kt <= qt; kt++) {
        cp_wait<0>();
        __syncthreads();
        if (kt < qt) load_kv((kt + 1) & 1, kt + 1);
        cp_commit();

        if (kt == 0) {
            const float* Aq0 = Qs + r0w * 192;
            const float* Aq8 = Qs + (r0w + 8) * 192;
#pragma unroll
            for (int s = 0; s < 24; s++) {
                int k = s * 8 + (lane & 3);
                qf[s][0] = fbits(Aq0[k ^ swa]);
                qf[s][1] = fbits(Aq8[k ^ swa]);
                qf[s][2] = fbits(Aq0[(k + 4) ^ swa]);
                qf[s][3] = fbits(Aq8[(k + 4) ^ swa]);
            }
        }

        const float* Kb = Ks + (kt & 1) * AQ;
        const float* Vb = Vs + (kt & 1) * AV;

        float sacc[4][4];
#pragma unroll
        for (int i = 0; i < 4; i++)
#pragma unroll
            for (int j = 0; j < 4; j++) sacc[i][j] = 0.f;

#pragma unroll 4
        for (int s = 0; s < 24; s++) {
            int k = s * 8 + (lane & 3);
#pragma unroll
            for (int nf = 0; nf < 4; nf++) {
                const float* pb = Kb + (wn * 32 + nf * 8 + (lane >> 2)) * 192;
                unsigned b[2] = { fbits(pb[k ^ swa]), fbits(pb[(k + 4) ^ swa]) };
                mma_tf32(sacc[nf], qf[s], b);
            }
        }
#pragma unroll
        for (int nf = 0; nf < 4; nf++) {
            int c = wn * 32 + nf * 8 + 2 * (lane & 3);
            Ps[r0w * APP + c] = sacc[nf][0];
            Ps[r0w * APP + c + 1] = sacc[nf][1];
            Ps[(r0w + 8) * APP + c] = sacc[nf][2];
            Ps[(r0w + 8) * APP + c + 1] = sacc[nf][3];
        }
        __syncthreads();

        {
            int row = tid >> 2, sub = tid & 3;
            float* pr = Ps + row * APP + sub * 16;
            bool diag = (kt == qt);
            float v[16];
#pragma unroll
            for (int j = 0; j < 16; j++) {
                float x = pr[j];
                if (diag && (sub * 16 + j) > row) x = -1e30f;
                v[j] = x;
            }
            float mx = v[0];
#pragma unroll
            for (int j = 1; j < 16; j++) mx = fmaxf(mx, v[j]);
            mx = fmaxf(mx, __shfl_xor_sync(0xffffffffu, mx, 1));
            mx = fmaxf(mx, __shfl_xor_sync(0xffffffffu, mx, 2));
            float mo = m_s[row];
            float mn = fmaxf(mo, mx);
            float sum = 0.f;
#pragma unroll
            for (int j = 0; j < 16; j++) {
                float p = __expf((v[j] - mn) * SCALEF);
                sum += p;
                pr[j] = tf32r(p);
            }
            sum += __shfl_xor_sync(0xffffffffu, sum, 1);
            sum += __shfl_xor_sync(0xffffffffu, sum, 2);
            if (sub == 0) {
                float al = __expf((mo - mn) * SCALEF);
                al_s[row] = al;
                l_s[row] = l_s[row] * al + sum;
                m_s[row] = mn;
            }
        }
        __syncthreads();

        {
            float al0 = al_s[r0w], al1 = al_s[r0w + 8];
#pragma unroll
            for (int nf = 0; nf < 8; nf++) {
                oacc[nf][0] *= al0; oacc[nf][1] *= al0;
                oacc[nf][2] *= al1; oacc[nf][3] *= al1;
            }
            const float* Ap0 = Ps + r0w * APP + (lane & 3);
            int swv = 8 * (lane & 3);
#pragma unroll
            for (int k0 = 0; k0 < 64; k0 += 8) {
                unsigned a[4];
                a[0] = fbits(Ap0[k0]);
                a[1] = fbits(Ap0[k0 + 8 * APP]);
                a[2] = fbits(Ap0[k0 + 4]);
                a[3] = fbits(Ap0[k0 + 4 + 8 * APP]);
                int kr = k0 + (lane & 3);
                const float* Vr0 = Vb + kr * 128;
                const float* Vr4 = Vb + (kr + 4) * 128;
#pragma unroll
                for (int nf = 0; nf < 8; nf++) {
                    int col = wn * 64 + nf * 8 + (lane >> 2);
                    unsigned b[2] = { fbits(Vr0[col ^ swv]), fbits(Vr4[col ^ swv]) };
                    mma_tf32(oacc[nf], a, b);
                }
            }
        }
    }

    // epilogue: divide by l, write fp16 y (feeds fp16 wo GEMM)
    {
        float inv0 = 1.f / l_s[r0w], inv1 = 1.f / l_s[r0w + 8];
        int t0 = qt * 64 + r0w;
#pragma unroll
        for (int nf = 0; nf < 8; nf++) {
            int c = wn * 64 + nf * 8 + 2 * (lane & 3);
            __half2* y0 = (__half2*)(y + (size_t)t0 * CC + h * DV + c);
            __half2* y1 = (__half2*)(y + (size_t)(t0 + 8) * CC + h * DV + c);
            *y0 = __floats2half2_rn(oacc[nf][0] * inv0, oacc[nf][1] * inv0);
            *y1 = __floats2half2_rn(oacc[nf][2] * inv1, oacc[nf][3] * inv1);
        }
    }
}

// ---------------- launch ----------------
extern "C" void kernel_launch(void* const* d_in, const int* in_sizes, int n_in,
                              void* d_out, int out_size) {
    const float* x        = (const float*)d_in[0];
    const float* freqs    = (const float*)d_in[1];
    const float* wq_a     = (const float*)d_in[2];
    const float* bq_a     = (const float*)d_in[3];
    const float* q_norm_w = (const float*)d_in[4];
    const float* wq_b     = (const float*)d_in[5];
    const float* bq_b     = (const float*)d_in[6];
    const float* wkv_a    = (const float*)d_in[7];
    const float* bkv_a    = (const float*)d_in[8];
    const float* kv_norm_w= (const float*)d_in[9];
    const float* wkv_b    = (const float*)d_in[10];
    const float* bkv_b    = (const float*)d_in[11];
    const float* wo       = (const float*)d_in[12];
    const float* bo       = (const float*)d_in[13];
    float* out = (float*)d_out;

    float *qlat, *qbuf, *kvpe, *kvb;
    __half *qlat_h, *kvlat_h, *yh, *hx, *hwqa, *hwqb, *hwkva, *hwkvb, *hwo;
    cudaGetSymbolAddress((void**)&qlat,   g_qlat);
    cudaGetSymbolAddress((void**)&qbuf,   g_q);
    cudaGetSymbolAddress((void**)&kvpe,   g_kvpe);
    cudaGetSymbolAddress((void**)&kvb,    g_kvb);
    cudaGetSymbolAddress((void**)&qlat_h, g_qlat_h);
    cudaGetSymbolAddress((void**)&kvlat_h,g_kvlat_h);
    cudaGetSymbolAddress((void**)&yh,     g_yh);
    cudaGetSymbolAddress((void**)&hx,     g_hx);
    cudaGetSymbolAddress((void**)&hwqa,   g_hwqa);
    cudaGetSymbolAddress((void**)&hwqb,   g_hwqb);
    cudaGetSymbolAddress((void**)&hwkva,  g_hwkva);
    cudaGetSymbolAddress((void**)&hwkvb,  g_hwkvb);
    cudaGetSymbolAddress((void**)&hwo,    g_hwo);

    cudaFuncSetAttribute((const void*)gemm_a_merged, cudaFuncAttributeMaxDynamicSharedMemorySize, gsmemh(4));
    cudaFuncSetAttribute((const void*)gemm_b_merged, cudaFuncAttributeMaxDynamicSharedMemorySize, gsmemh(8));
    cudaFuncSetAttribute((const void*)gemm_wo,       cudaFuncAttributeMaxDynamicSharedMemorySize, gsmemh(8));
    cudaFuncSetAttribute((const void*)attn_tc,       cudaFuncAttributeMaxDynamicSharedMemorySize, ATTN_SMEM);

    // 0. fp32 -> fp16 conversion of x + all weights
    C6 P;
    P.g[0] = { x,     hx,    (unsigned)(TT * CC / 4) };
    P.g[1] = { wq_a,  hwqa,  (unsigned)(RQ * CC / 4) };
    P.g[2] = { wq_b,  hwqb,  (unsigned)(HH * QKD * RQ / 4) };
    P.g[3] = { wkv_a, hwkva, (unsigned)((RKV + DR) * CC / 4) };
    P.g[4] = { wkv_b, hwkvb, (unsigned)(HH * (DN + DV) * RKV / 4) };
    P.g[5] = { wo,    hwo,   (unsigned)(CC * CC / 4) };
    conv_all<<<2048, 256>>>(P);

    // 1. both A-projections (fp16 mma), one packed launch
    gemm_a_merged<<<dim3(33, TT / 128), 128, gsmemh(4)>>>(hx, hwqa, bq_a, qlat, hwkva, bkv_a, kvpe);

    // 2. both rmsnorms (fp16 out) + rope_k
    rmsnorm_rope_merged<<<2 * TT, 256>>>(freqs, q_norm_w, kv_norm_w);

    // 3. both B-projections (fp16 mma), one packed launch
    gemm_b_merged<<<dim3(56, TT / 128), 128, gsmemh(8)>>>(qlat_h, hwqb, bq_b, qbuf, kvlat_h, hwkvb, bkv_b, kvb);

    // 4. rope on q
    rope_q_kernel<<<(TT * HH * 32 + 255) / 256, 256>>>(freqs);

    // 5. attention (tf32, unchanged; fp16 epilogue)
    attn_tc<<<dim3(TT / 64, HH), 256, ATTN_SMEM>>>(qbuf, kvb, kvpe, yh);

    // 6. output projection (fp16 mma)
    gemm_wo<<<dim3(CC / 128, TT / 128), 128, gsmemh(8)>>>(yh, hwo, bo, out);
}